// round 5
// baseline (speedup 1.0000x reference)
#include <cuda_runtime.h>
#include <math.h>

// ------------------------- problem constants -------------------------
constexpr int kNI = 8192, kND = 4096, kNT = 12288, kD = 256, kH = 4, kDH = 64;
constexpr int kB = 8, kKP = 768;
constexpr int kEC = 65536, kEI = 32768, kEO = 32768, kEK = 8192;
constexpr long LXD = (long)kNT * kD;          // full node-feature buffer
constexpr long LPD = (long)kB * kKP * kD;     // pooled buffer

// ------------------------- scratch (static device memory) -------------------------
struct Scratch {
    float x[LXD], yF[LXD], yR[LXD], Kb[LXD], Qb[LXD], Vb[LXD], agg[LXD];
    float Krel[4L * kNI * kD], Vrel[4L * kNI * kD];
    float S[(long)kB * kH * kKP * kKP];
    float xp[LPD], qb[LPD], kb[LPD], vb[LPD], oh[LPD], yb[LPD], ga[LPD];
    float hv[kNT], sc[kNT];
    float sv[kB * kKP];
    int   si[kB * kKP];
    float u[2 * kB * 512];
    int rpf0[kNI + 1], rpf1[kND + 1], rpr0[kNI + 1], rpr1[kND + 1], rph[kNT + 1];
    int ef0[kEC + kEI + kEK], ef1[kEO], er0[kEC + kEO + kEK], er1[kEI];
    int eh[kEC + kEI + kEO + kEK + kNT];
    int cnt[kNT], cur[kNT];
};
__device__ Scratch SC;

// ------------------------- reductions -------------------------
__device__ __forceinline__ float wsum(float v) {
#pragma unroll
    for (int o = 16; o; o >>= 1) v += __shfl_xor_sync(0xffffffffu, v, o);
    return v;
}
__device__ __forceinline__ float bsum(float v) {
    __shared__ float sh[32];
    int lane = threadIdx.x & 31, w = threadIdx.x >> 5;
    v = wsum(v);
    if (!lane) sh[w] = v;
    __syncthreads();
    int nw = blockDim.x >> 5;
    float s = (threadIdx.x < nw) ? sh[threadIdx.x] : 0.f;
    if (w == 0) s = wsum(s);
    if (threadIdx.x == 0) sh[0] = s;
    __syncthreads();
    float r = sh[0];
    __syncthreads();
    return r;
}
__device__ __forceinline__ float bmax(float v) {
    __shared__ float sh[32];
    int lane = threadIdx.x & 31, w = threadIdx.x >> 5;
#pragma unroll
    for (int o = 16; o; o >>= 1) v = fmaxf(v, __shfl_xor_sync(0xffffffffu, v, o));
    if (!lane) sh[w] = v;
    __syncthreads();
    int nw = blockDim.x >> 5;
    float s = (threadIdx.x < nw) ? sh[threadIdx.x] : -INFINITY;
    if (w == 0)
#pragma unroll
        for (int o = 16; o; o >>= 1) s = fmaxf(s, __shfl_xor_sync(0xffffffffu, s, o));
    if (threadIdx.x == 0) sh[0] = s;
    __syncthreads();
    float r = sh[0];
    __syncthreads();
    return r;
}

// ------------------------- generic 64x64x16 fp32 GEMM -------------------------
// C = epilogue(alpha * A @ B(^T)); z-batched: z -> (zb = z/ZH, zh = z%ZH).
// mode 0: C = v
// mode 1: C = g*v + (1-g)*Add,  g = sigmoid(*gptr)
// mode 2: C = v + Add
template <bool TB>
__global__ void __launch_bounds__(256) gemm_k(
    const float* __restrict__ A, int lda, long Ab, long Ah,
    const float* __restrict__ Bm, int ldb, long Bb, long Bh,
    float* __restrict__ C, int ldc, long Cb, long Ch,
    const float* __restrict__ Add, int ldadd, const float* __restrict__ gptr,
    int Kdim, int ZH, float alpha, int mode)
{
    __shared__ float As[16][72];
    __shared__ float Bs[16][72];
    int z = blockIdx.z, zb = z / ZH, zh = z - zb * ZH;
    A += zb * Ab + zh * Ah;
    Bm += zb * Bb + zh * Bh;
    C += zb * Cb + zh * Ch;
    int m0 = blockIdx.x * 64, n0 = blockIdx.y * 64;
    int tid = threadIdx.x, tx = tid & 15, ty = tid >> 4;
    float acc[4][4] = {};
    int aR = tid >> 2, aK = (tid & 3) * 4;
    int bR = tid >> 4, bC = (tid & 15) * 4;
    for (int k0 = 0; k0 < Kdim; k0 += 16) {
        float4 av = *(const float4*)(A + (long)(m0 + aR) * lda + k0 + aK);
        As[aK + 0][aR] = av.x; As[aK + 1][aR] = av.y;
        As[aK + 2][aR] = av.z; As[aK + 3][aR] = av.w;
        if (TB) {
            float4 bv = *(const float4*)(Bm + (long)(n0 + aR) * ldb + k0 + aK);
            Bs[aK + 0][aR] = bv.x; Bs[aK + 1][aR] = bv.y;
            Bs[aK + 2][aR] = bv.z; Bs[aK + 3][aR] = bv.w;
        } else {
            *(float4*)&Bs[bR][bC] = *(const float4*)(Bm + (long)(k0 + bR) * ldb + n0 + bC);
        }
        __syncthreads();
#pragma unroll
        for (int kk = 0; kk < 16; kk++) {
            float4 a = *(const float4*)&As[kk][ty * 4];
            float4 b = *(const float4*)&Bs[kk][tx * 4];
            acc[0][0] += a.x * b.x; acc[0][1] += a.x * b.y; acc[0][2] += a.x * b.z; acc[0][3] += a.x * b.w;
            acc[1][0] += a.y * b.x; acc[1][1] += a.y * b.y; acc[1][2] += a.y * b.z; acc[1][3] += a.y * b.w;
            acc[2][0] += a.z * b.x; acc[2][1] += a.z * b.y; acc[2][2] += a.z * b.z; acc[2][3] += a.z * b.w;
            acc[3][0] += a.w * b.x; acc[3][1] += a.w * b.y; acc[3][2] += a.w * b.z; acc[3][3] += a.w * b.w;
        }
        __syncthreads();
    }
    float g = 1.f;
    if (mode == 1) g = 1.f / (1.f + expf(-gptr[0]));
#pragma unroll
    for (int i = 0; i < 4; i++)
#pragma unroll
        for (int j = 0; j < 4; j++) {
            long r = m0 + ty * 4 + i, c = n0 + tx * 4 + j;
            float v = alpha * acc[i][j];
            if (mode == 1) v = g * v + (1.f - g) * Add[r * ldadd + c];
            else if (mode == 2) v = v + Add[r * ldadd + c];
            C[r * ldc + c] = v;
        }
}

// ------------------------- elementwise kernels -------------------------
__global__ void gelu_k(const float* __restrict__ in, float* __restrict__ out, long n) {
    long i = (long)blockIdx.x * blockDim.x + threadIdx.x;
    if (i < n) {
        float v = in[i];
        out[i] = 0.5f * v * (1.f + erff(v * 0.7071067811865475f));
    }
}
__global__ void comb_relu_k(const float* __restrict__ a, const float* __restrict__ b,
                            float* __restrict__ x, long n) {
    long i = (long)blockIdx.x * blockDim.x + threadIdx.x;
    if (i < n) {
        float v = 0.5f * a[i] + 0.5f * b[i];
        x[i] = v > 0.f ? v : 0.f;
    }
}

// ------------------------- CSR construction -------------------------
__global__ void zero_k(int* p, int n) {
    int i = blockIdx.x * blockDim.x + threadIdx.x;
    if (i < n) p[i] = 0;
}
__global__ void count_k(const int* __restrict__ dst, int E, int doff, int* cnt) {
    int i = blockIdx.x * blockDim.x + threadIdx.x;
    if (i < E) atomicAdd(&cnt[dst[i] + doff], 1);
}
__global__ void loop_count_k(int* cnt, int n) {
    int i = blockIdx.x * blockDim.x + threadIdx.x;
    if (i < n) cnt[i] += 1;
}
__global__ void scan_k(const int* __restrict__ cnt, int* __restrict__ rp, int n) {
    __shared__ int sh[1024];
    int t = threadIdx.x;
    int c = (n + 1023) >> 10;
    int beg = t * c, end = min(beg + c, n);
    int s = 0;
    for (int i = beg; i < end; i++) s += cnt[i];
    sh[t] = s;
    __syncthreads();
    for (int off = 1; off < 1024; off <<= 1) {
        int v = (t >= off) ? sh[t - off] : 0;
        __syncthreads();
        sh[t] += v;
        __syncthreads();
    }
    int run = t ? sh[t - 1] : 0;
    for (int i = beg; i < end; i++) { rp[i] = run; run += cnt[i]; }
    if (t == 1023) rp[n] = sh[1023];
}
__global__ void copy_k(const int* a, int* b, int n) {
    int i = blockIdx.x * blockDim.x + threadIdx.x;
    if (i < n) b[i] = a[i];
}
__global__ void fill_k(const int* __restrict__ src, const int* __restrict__ dst, int E,
                       int soff, int doff, int tag, int* cur, int* __restrict__ ent) {
    int i = blockIdx.x * blockDim.x + threadIdx.x;
    if (i < E) {
        int pos = atomicAdd(&cur[dst[i] + doff], 1);
        ent[pos] = (tag << 16) | (src[i] + soff);
    }
}
__global__ void loop_fill_k(int n, int* cur, int* __restrict__ ent) {
    int i = blockIdx.x * blockDim.x + threadIdx.x;
    if (i < n) {
        int pos = atomicAdd(&cur[i], 1);
        ent[pos] = i;
    }
}

// ------------------------- HGT softmax aggregation -------------------------
// One block per dst node; warp h handles head h (online softmax over incoming edges).
__global__ void hgt_agg_k(const float* __restrict__ Q, const float* __restrict__ Krel,
                          const float* __restrict__ Vrel, const int* __restrict__ rp,
                          const int* __restrict__ ent, const float* __restrict__ prel,
                          float* __restrict__ agg, int dstBase)
{
    int node = blockIdx.x;
    int h = threadIdx.x >> 5, lane = threadIdx.x & 31;
    const float* q = Q + (long)(dstBase + node) * kD + h * kDH;
    float q0 = q[lane], q1 = q[lane + 32];
    float pr0 = prel[0 * kH + h], pr1 = prel[1 * kH + h];
    float pr2 = prel[2 * kH + h], pr3 = prel[3 * kH + h];
    int s = rp[node], e1 = rp[node + 1];
    float m = -INFINITY, den = 0.f, a0 = 0.f, a1 = 0.f;
    for (int e = s; e < e1; e++) {
        int pk = ent[e];
        int r = pk >> 16, src = pk & 0xffff;
        const float* kr = Krel + ((long)r * kNI + src) * kD + h * kDH;
        float d0 = q0 * kr[lane] + q1 * kr[lane + 32];
        d0 = wsum(d0);
        float pr = (r == 0) ? pr0 : (r == 1) ? pr1 : (r == 2) ? pr2 : pr3;
        float sc2 = d0 * pr * 0.125f;
        float mn = fmaxf(m, sc2);
        float cc = expf(m - mn), w = expf(sc2 - mn);
        const float* vr = Vrel + ((long)r * kNI + src) * kD + h * kDH;
        den = den * cc + w;
        a0 = a0 * cc + w * vr[lane];
        a1 = a1 * cc + w * vr[lane + 32];
        m = mn;
    }
    float inv = 1.f / (den + 1e-16f);
    float* o = agg + (long)(dstBase + node) * kD + h * kDH;
    o[lane] = a0 * inv;
    o[lane + 32] = a1 * inv;
}

// ------------------------- pooling -------------------------
__global__ void hv_k(const float* __restrict__ x, const float* __restrict__ pw,
                     float* __restrict__ hv) {
    int node = blockIdx.x * 8 + (threadIdx.x >> 5);
    int lane = threadIdx.x & 31;
    if (node >= kNT) return;
    float s = 0.f;
    for (int d = lane; d < kD; d += 32) s += x[(long)node * kD + d] * pw[d];
    s = wsum(s);
    if (!lane) hv[node] = s;
}
__global__ void gat_score_k(const float* __restrict__ hv, const int* __restrict__ rp,
                            const int* __restrict__ ent, const float* __restrict__ att,
                            const float* __restrict__ bias, float* __restrict__ sc) {
    int i = blockIdx.x * blockDim.x + threadIdx.x;
    if (i >= kNT) return;
    float A0 = att[0], A1 = att[1];
    float hi = hv[i];
    int s = rp[i], e1 = rp[i + 1];
    float m = -INFINITY, den = 0.f, acc = 0.f;
    for (int e = s; e < e1; e++) {
        int src = ent[e] & 0xffff;
        float hs = hv[src];
        float ee = A0 * hs + A1 * hi;
        ee = ee >= 0.f ? ee : 0.2f * ee;
        float mn = fmaxf(m, ee);
        float c = expf(m - mn), w = expf(ee - mn);
        den = den * c + w;
        acc = acc * c + w * hs;
        m = mn;
    }
    sc[i] = acc / (den + 1e-16f) + bias[0];
}

// Bitonic sort of 1536 (padded to 2048) per graph; descending, ties -> lower index.
__global__ void topk_sort_k(const float* __restrict__ sc, float* __restrict__ sv,
                            int* __restrict__ si) {
    int b = blockIdx.x, t = threadIdx.x;
    __shared__ float v[2048];
    __shared__ int ix[2048];
    for (int p = t; p < 2048; p += 1024) {
        float val = -INFINITY;
        if (p < 1536) {
            int node = p < 1024 ? b * 1024 + p : kNI + b * 512 + (p - 1024);
            val = sc[node];
        }
        v[p] = val;
        ix[p] = p;
    }
    __syncthreads();
    for (int k = 2; k <= 2048; k <<= 1)
        for (int j = k >> 1; j > 0; j >>= 1) {
#pragma unroll
            for (int pass = 0; pass < 2; pass++) {
                int i = t + pass * 1024;
                int l = i ^ j;
                if (l > i) {
                    bool up = ((i & k) == 0);
                    float vi = v[i], vl = v[l];
                    int ii = ix[i], il = ix[l];
                    bool before = (vi > vl) || (vi == vl && ii < il);
                    if (up != before) {
                        v[i] = vl; v[l] = vi;
                        ix[i] = il; ix[l] = ii;
                    }
                }
            }
            __syncthreads();
        }
    if (t < kKP) {
        sv[b * kKP + t] = v[t];
        si[b * kKP + t] = ix[t];
    }
}
__global__ void gather_k(const float* __restrict__ x, const float* __restrict__ sv,
                         const int* __restrict__ si, float* __restrict__ xp) {
    int q = blockIdx.x, b = blockIdx.y, d = threadIdx.x;
    int j = si[b * kKP + q];
    float tv = tanhf(sv[b * kKP + q]);
    int node = j < 1024 ? b * 1024 + j : kNI + b * 512 + (j - 1024);
    xp[((long)(b * kKP + q)) * kD + d] = x[(long)node * kD + d] * tv;
}

// ------------------------- transformer pieces -------------------------
__global__ void softmax_k(float* __restrict__ S) {
    long row = blockIdx.x;
    float* p = S + row * kKP;
    int t = threadIdx.x;
    float m = -INFINITY;
    for (int i = t; i < kKP; i += 256) m = fmaxf(m, p[i]);
    m = bmax(m);
    float s = 0.f;
    for (int i = t; i < kKP; i += 256) {
        float e = expf(p[i] - m);
        p[i] = e;
        s += e;
    }
    s = bsum(s);
    float inv = 1.f / s;
    for (int i = t; i < kKP; i += 256) p[i] *= inv;
}
__global__ void ln_k(const float* __restrict__ y, const float* __restrict__ g,
                     const float* __restrict__ bta, float* __restrict__ out) {
    long row = blockIdx.x;
    int d = threadIdx.x;
    float v = y[row * kD + d];
    float mu = bsum(v) * (1.f / kD);
    float df = v - mu;
    float var = bsum(df * df) * (1.f / kD);
    out[row * kD + d] = g[d] * df * rsqrtf(var + 1e-5f) + bta[d];
}
__global__ void featsum_k(const float* __restrict__ xp, const float* __restrict__ ga,
                          float* __restrict__ u) {
    int b = blockIdx.x, d = threadIdx.x;
    float s1 = 0.f, s2 = 0.f;
    for (int q = 0; q < kKP; q++) {
        long o = ((long)(b * kKP + q)) * kD + d;
        s1 += xp[o];
        s2 += ga[o];
    }
    u[b * 512 + d] = s1;
    u[b * 512 + 256 + d] = s2;
}
__global__ void cos_k(const float* __restrict__ u, float* __restrict__ out) {
    int b = blockIdx.x, t = threadIdx.x;
    float a = u[b * 512 + t];
    float c = u[(kB + b) * 512 + t];
    float dot = bsum(a * c);
    float na = bsum(a * a);
    float nc = bsum(c * c);
    if (t == 0)
        out[b] = dot / (fmaxf(sqrtf(na), 1e-8f) * fmaxf(sqrtf(nc), 1e-8f));
}

// ------------------------- host orchestration -------------------------
static inline void gemm(bool tb, const float* A, int lda, long Ab, long Ah,
                        const float* Bm, int ldb, long Bb, long Bh,
                        float* C, int ldc, long Cb, long Ch,
                        const float* Add, int ldadd, const float* gptr,
                        int M, int N, int K, int ZB, int ZH, float alpha, int mode) {
    dim3 g(M / 64, N / 64, ZB * ZH), blk(256);
    if (tb)
        gemm_k<true><<<g, blk>>>(A, lda, Ab, Ah, Bm, ldb, Bb, Bh, C, ldc, Cb, Ch,
                                 Add, ldadd, gptr, K, ZH, alpha, mode);
    else
        gemm_k<false><<<g, blk>>>(A, lda, Ab, Ah, Bm, ldb, Bb, Bh, C, ldc, Cb, Ch,
                                  Add, ldadd, gptr, K, ZH, alpha, mode);
}

struct EdgeSpec { const int* src; const int* dst; int E, soff, doff, tag; };

static void build_csr(int n, int* rp, int* ent, int* cnt, int* cur,
                      const EdgeSpec* es, int ns, bool loops) {
    zero_k<<<(n + 255) / 256, 256>>>(cnt, n);
    for (int i = 0; i < ns; i++)
        count_k<<<(es[i].E + 255) / 256, 256>>>(es[i].dst, es[i].E, es[i].doff, cnt);
    if (loops) loop_count_k<<<(n + 255) / 256, 256>>>(cnt, n);
    scan_k<<<1, 1024>>>(cnt, rp, n);
    copy_k<<<(n + 255) / 256, 256>>>(rp, cur, n);
    for (int i = 0; i < ns; i++)
        fill_k<<<(es[i].E + 255) / 256, 256>>>(es[i].src, es[i].dst, es[i].E,
                                               es[i].soff, es[i].doff, es[i].tag, cur, ent);
    if (loops) loop_fill_k<<<(n + 255) / 256, 256>>>(n, cur, ent);
}

static void run_branch(Scratch* sp, const float* xi, const float* xd,
                       const int* ec, const int* ei, const int* eo, const int* ek,
                       const float* Wk, const float* Wq, const float* Wv, const float* Wo,
                       const float* arel, const float* mrel, const float* prel,
                       const float* skip, const float* poolW, const float* poolAtt,
                       const float* poolBias, const float* tWq, const float* tWk,
                       const float* tWv, const float* tWo, const float* lng,
                       const float* lnb, int branch)
{
    const long DD = (long)kD * kD;
    const long T1 = (long)kNI * kD;    // type-1 offset in node buffers

    // assemble x = [x_inst ; x_data]
    cudaMemcpyAsync(sp->x, xi, T1 * sizeof(float), cudaMemcpyDeviceToDevice, 0);
    cudaMemcpyAsync(sp->x + T1, xd, (long)kND * kD * sizeof(float),
                    cudaMemcpyDeviceToDevice, 0);

    const int *rc = ec, *cc = ec + kEC;
    const int *ri = ei, *ci = ei + kEI;
    const int *ro = eo, *co = eo + kEO;
    const int *rk = ek, *ck = ek + kEK;

    // HGT CSRs (type-local indices; tag = relation id)
    { EdgeSpec e[3] = { {rc, cc, kEC, 0, 0, 0}, {ri, ci, kEI, 0, 0, 1}, {rk, ck, kEK, 0, 0, 3} };
      build_csr(kNI, sp->rpf0, sp->ef0, sp->cnt, sp->cur, e, 3, false); }
    { EdgeSpec e[1] = { {ro, co, kEO, 0, 0, 2} };
      build_csr(kND, sp->rpf1, sp->ef1, sp->cnt, sp->cur, e, 1, false); }
    { EdgeSpec e[3] = { {cc, rc, kEC, 0, 0, 0}, {co, ro, kEO, 0, 0, 2}, {ck, rk, kEK, 0, 0, 3} };
      build_csr(kNI, sp->rpr0, sp->er0, sp->cnt, sp->cur, e, 3, false); }
    { EdgeSpec e[1] = { {ci, ri, kEI, 0, 0, 1} };
      build_csr(kND, sp->rpr1, sp->er1, sp->cnt, sp->cur, e, 1, false); }
    // homogeneous CSR for pooling GAT (inst first, data offset +kNI, self-loops)
    { EdgeSpec e[4] = { {rc, cc, kEC, 0, 0, 0}, {ri, ci, kEI, kNI, 0, 0},
                        {ro, co, kEO, 0, kNI, 0}, {rk, ck, kEK, 0, 0, 0} };
      build_csr(kNT, sp->rph, sp->eh, sp->cnt, sp->cur, e, 4, true); }

    static const int fwdsrc[4] = {0, 1, 0, 0};
    static const int revsrc[4] = {0, 0, 1, 0};

    for (int l = 0; l < 2; l++) {
        for (int dir = 0; dir < 2; dir++) {
            long wOff = (long)((l * 2 + dir) * 2) * DD;
            // K, Q, V per node type
            for (int t = 0; t < 2; t++) {
                const float* xb = sp->x + (t ? T1 : 0);
                int M = t ? kND : kNI;
                long tOff = t ? T1 : 0;
                gemm(false, xb, kD, 0, 0, Wk + wOff + t * DD, kD, 0, 0,
                     sp->Kb + tOff, kD, 0, 0, nullptr, 0, nullptr,
                     M, kD, kD, 1, 1, 1.f, 0);
                gemm(false, xb, kD, 0, 0, Wq + wOff + t * DD, kD, 0, 0,
                     sp->Qb + tOff, kD, 0, 0, nullptr, 0, nullptr,
                     M, kD, kD, 1, 1, 1.f, 0);
                gemm(false, xb, kD, 0, 0, Wv + wOff + t * DD, kD, 0, 0,
                     sp->Vb + tOff, kD, 0, 0, nullptr, 0, nullptr,
                     M, kD, kD, 1, 1, 1.f, 0);
            }
            // Krel / Vrel (per-relation per-head 64x64 transforms, z-batched over heads)
            for (int r = 0; r < 4; r++) {
                int st = dir ? revsrc[r] : fwdsrc[r];
                int M = st ? kND : kNI;
                long sOff = st ? T1 : 0;
                long relOff = (long)(((l * 2 + dir) * 4 + r) * kH) * kDH * kDH;
                gemm(false, sp->Kb + sOff, kD, 0, 64, arel + relOff, kDH, 0, (long)kDH * kDH,
                     sp->Krel + (long)r * kNI * kD, kD, 0, 64, nullptr, 0, nullptr,
                     M, kDH, kDH, 1, kH, 1.f, 0);
                gemm(false, sp->Vb + sOff, kD, 0, 64, mrel + relOff, kDH, 0, (long)kDH * kDH,
                     sp->Vrel + (long)r * kNI * kD, kD, 0, 64, nullptr, 0, nullptr,
                     M, kDH, kDH, 1, kH, 1.f, 0);
            }
            // aggregation
            const float* prelp = prel + (long)((l * 2 + dir) * 4) * kH;
            if (dir == 0) {
                hgt_agg_k<<<kNI, 128>>>(sp->Qb, sp->Krel, sp->Vrel, sp->rpf0, sp->ef0,
                                        prelp, sp->agg, 0);
                hgt_agg_k<<<kND, 128>>>(sp->Qb, sp->Krel, sp->Vrel, sp->rpf1, sp->ef1,
                                        prelp, sp->agg, kNI);
            } else {
                hgt_agg_k<<<kNI, 128>>>(sp->Qb, sp->Krel, sp->Vrel, sp->rpr0, sp->er0,
                                        prelp, sp->agg, 0);
                hgt_agg_k<<<kND, 128>>>(sp->Qb, sp->Krel, sp->Vrel, sp->rpr1, sp->er1,
                                        prelp, sp->agg, kNI);
            }
            // gelu -> Kb (Kb no longer needed), then Wo with sigmoid-skip blend
            gelu_k<<<(int)(LXD / 256), 256>>>(sp->agg, sp->Kb, LXD);
            float* yD = dir ? sp->yR : sp->yF;
            for (int t = 0; t < 2; t++) {
                int M = t ? kND : kNI;
                long tOff = t ? T1 : 0;
                gemm(false, sp->Kb + tOff, kD, 0, 0, Wo + wOff + t * DD, kD, 0, 0,
                     yD + tOff, kD, 0, 0, sp->x + tOff, kD,
                     skip + (l * 2 + dir) * 2 + t, M, kD, kD, 1, 1, 1.f, 1);
            }
        }
        comb_relu_k<<<(int)(LXD / 256), 256>>>(sp->yF, sp->yR, sp->x, LXD);
    }

    // pooling
    hv_k<<<kNT / 8, 256>>>(sp->x, poolW, sp->hv);
    gat_score_k<<<(kNT + 255) / 256, 256>>>(sp->hv, sp->rph, sp->eh, poolAtt, poolBias, sp->sc);
    topk_sort_k<<<kB, 1024>>>(sp->sc, sp->sv, sp->si);
    gather_k<<<dim3(kKP, kB), kD>>>(sp->x, sp->sv, sp->si, sp->xp);

    // transformer attention over pooled nodes
    int Mp = kB * kKP;
    gemm(false, sp->xp, kD, 0, 0, tWq, kD, 0, 0, sp->qb, kD, 0, 0,
         nullptr, 0, nullptr, Mp, kD, kD, 1, 1, 1.f, 0);
    gemm(false, sp->xp, kD, 0, 0, tWk, kD, 0, 0, sp->kb, kD, 0, 0,
         nullptr, 0, nullptr, Mp, kD, kD, 1, 1, 1.f, 0);
    gemm(false, sp->xp, kD, 0, 0, tWv, kD, 0, 0, sp->vb, kD, 0, 0,
         nullptr, 0, nullptr, Mp, kD, kD, 1, 1, 1.f, 0);
    long pb = (long)kKP * kD;              // per-graph stride in pooled buffers
    long sb = (long)kH * kKP * kKP;        // per-graph stride in S
    gemm(true, sp->qb, kD, pb, kDH, sp->kb, kD, pb, kDH,
         sp->S, kKP, sb, (long)kKP * kKP, nullptr, 0, nullptr,
         kKP, kKP, kDH, kB, kH, 0.125f, 0);
    softmax_k<<<kB * kH * kKP, 256>>>(sp->S);
    gemm(false, sp->S, kKP, sb, (long)kKP * kKP, sp->vb, kD, pb, kDH,
         sp->oh, kD, pb, kDH, nullptr, 0, nullptr,
         kKP, kDH, kKP, kB, kH, 1.f, 0);
    gemm(false, sp->oh, kD, 0, 0, tWo, kD, 0, 0, sp->yb, kD, 0, 0,
         sp->xp, kD, nullptr, Mp, kD, kD, 1, 1, 1.f, 2);
    ln_k<<<Mp, kD>>>(sp->yb, lng, lnb, sp->ga);
    featsum_k<<<kB, kD>>>(sp->xp, sp->ga, sp->u + (long)branch * kB * 512);
}

extern "C" void kernel_launch(void* const* d_in, const int* in_sizes, int n_in,
                              void* d_out, int out_size) {
    Scratch* sp = nullptr;
    cudaGetSymbolAddress((void**)&sp, SC);

    const float* Wk    = (const float*)d_in[12];
    const float* Wq    = (const float*)d_in[13];
    const float* Wv    = (const float*)d_in[14];
    const float* Wo    = (const float*)d_in[15];
    const float* arel  = (const float*)d_in[16];
    const float* mrel  = (const float*)d_in[17];
    const float* prel  = (const float*)d_in[18];
    const float* skip  = (const float*)d_in[19];
    const float* poolW = (const float*)d_in[20];
    const float* poolA = (const float*)d_in[21];
    const float* poolB = (const float*)d_in[22];
    const float* tWq   = (const float*)d_in[23];
    const float* tWk   = (const float*)d_in[24];
    const float* tWv   = (const float*)d_in[25];
    const float* tWo   = (const float*)d_in[26];
    const float* lng   = (const float*)d_in[27];
    const float* lnb   = (const float*)d_in[28];

    for (int g = 0; g < 2; g++) {
        int base = g * 6;
        run_branch(sp,
                   (const float*)d_in[base + 0], (const float*)d_in[base + 1],
                   (const int*)d_in[base + 2], (const int*)d_in[base + 3],
                   (const int*)d_in[base + 4], (const int*)d_in[base + 5],
                   Wk, Wq, Wv, Wo, arel, mrel, prel, skip,
                   poolW, poolA, poolB, tWq, tWk, tWv, tWo, lng, lnb, g);
    }
    cos_k<<<kB, 512>>>(sp->u, (float*)d_out);
}